// round 1
// baseline (speedup 1.0000x reference)
#include <cuda_runtime.h>

// GlobalFilter: y = irfft2(rfft2(x, ortho) * W, ortho), spatial 14x14, B=256, C=512.
// Fully fused single kernel: per CTA = (one batch, 32 channels).
// Stage A : rfft along q (rows)            -> E[p][k2] complex in smem
// Stage B : fft along p + W mult + ifft p  -> overwrites E in place (no sync needed:
//            task (c,k2) reads/writes only column (.,k2,c))
// Stage A': irfft along q -> global y
// Normalization 1/196 folded into W at load time.

#define NC 32          // channels per CTA
#define NTHR 256

__global__ __launch_bounds__(NTHR) void gf_kernel(const float* __restrict__ x,
                                                  const float* __restrict__ w,
                                                  float* __restrict__ y) {
    extern __shared__ float sm[];
    float* xs = sm;                 // [196][NC]
    float* Er = xs + 196 * NC;      // [14][8][NC]
    float* Ei = Er + 14 * 8 * NC;   // [14][8][NC]

    const int b  = blockIdx.y;
    const int c0 = blockIdx.x * NC;
    const int tid = threadIdx.x;

    // cos/sin(2*pi*m/14), m = 0..13, as compile-time-foldable local constants
    const float CC[14] = {
         1.0000000000000000f,  0.9009688679024191f,  0.6234898018587336f,
         0.2225209339563144f, -0.2225209339563143f, -0.6234898018587335f,
        -0.9009688679024191f, -1.0000000000000000f, -0.9009688679024191f,
        -0.6234898018587336f, -0.2225209339563146f,  0.2225209339563143f,
         0.6234898018587334f,  0.9009688679024190f
    };
    const float SS[14] = {
         0.0000000000000000f,  0.4338837391175581f,  0.7818314824680298f,
         0.9749279121818236f,  0.9749279121818236f,  0.7818314824680299f,
         0.4338837391175582f,  0.0000000000000000f, -0.4338837391175581f,
        -0.7818314824680297f, -0.9749279121818236f, -0.9749279121818238f,
        -0.7818314824680300f, -0.4338837391175583f
    };

    // ---- Load x tile: x[b][n][c0..c0+31], n = 0..195, vectorized float4 ----
    {
        const float4* xin = reinterpret_cast<const float4*>(x + (b * 196) * 512 + c0);
        float4* xs4 = reinterpret_cast<float4*>(xs);
        // global row stride = 512 floats = 128 float4; tile row = NC/4 = 8 float4
        #pragma unroll 2
        for (int i = tid; i < 196 * (NC / 4); i += NTHR) {
            int n  = i >> 3;       // i / 8
            int c4 = i & 7;        // i % 8
            xs4[n * (NC / 4) + c4] = xin[n * 128 + c4];
        }
    }
    __syncthreads();

    // ---- Stage A: rfft along q for each (c, p). tasks = 14*NC = 448 ----
    for (int task = tid; task < 14 * NC; task += NTHR) {
        int c = task & (NC - 1);
        int p = task / NC;
        float xr[14];
        #pragma unroll
        for (int q = 0; q < 14; q++) xr[q] = xs[(p * 14 + q) * NC + c];
        #pragma unroll
        for (int k2 = 0; k2 < 8; k2++) {
            float er = 0.f, ei = 0.f;
            #pragma unroll
            for (int q = 0; q < 14; q++) {
                const int m = (k2 * q) % 14;
                er += xr[q] * CC[m];
                ei -= xr[q] * SS[m];
            }
            Er[(p * 8 + k2) * NC + c] = er;
            Ei[(p * 8 + k2) * NC + c] = ei;
        }
    }
    __syncthreads();

    // ---- Stage B fused: fft over p, multiply by W/196, ifft over p.
    //      tasks = 8*NC = 256 (exactly one per thread). In-place on E column. ----
    {
        int task = tid;                 // 8*NC == NTHR
        int c  = task & (NC - 1);
        int k2 = task / NC;
        float er[14], ei[14];
        #pragma unroll
        for (int p = 0; p < 14; p++) {
            er[p] = Er[(p * 8 + k2) * NC + c];
            ei[p] = Ei[(p * 8 + k2) * NC + c];
        }
        float zr[14], zi[14];
        // forward fft over p: e^{-i theta}
        #pragma unroll
        for (int k1 = 0; k1 < 14; k1++) {
            float ar = 0.f, ai = 0.f;
            #pragma unroll
            for (int p = 0; p < 14; p++) {
                const int m = (k1 * p) % 14;
                ar += er[p] * CC[m] + ei[p] * SS[m];
                ai += ei[p] * CC[m] - er[p] * SS[m];
            }
            zr[k1] = ar; zi[k1] = ai;
        }
        // pointwise complex weight, normalization folded in
        const float inv196 = 1.0f / 196.0f;
        #pragma unroll
        for (int k1 = 0; k1 < 14; k1++) {
            float2 wv = *reinterpret_cast<const float2*>(
                w + (((k1 * 8 + k2) * 512) + c0 + c) * 2);
            float wr = wv.x * inv196, wi = wv.y * inv196;
            float ar = zr[k1] * wr - zi[k1] * wi;
            float ai = zr[k1] * wi + zi[k1] * wr;
            zr[k1] = ar; zi[k1] = ai;
        }
        // inverse fft over p: e^{+i theta}
        #pragma unroll
        for (int p = 0; p < 14; p++) {
            float ar = 0.f, ai = 0.f;
            #pragma unroll
            for (int k1 = 0; k1 < 14; k1++) {
                const int m = (k1 * p) % 14;
                ar += zr[k1] * CC[m] - zi[k1] * SS[m];
                ai += zi[k1] * CC[m] + zr[k1] * SS[m];
            }
            Er[(p * 8 + k2) * NC + c] = ar;
            Ei[(p * 8 + k2) * NC + c] = ai;
        }
    }
    __syncthreads();

    // ---- Stage A': irfft along q (imag of k2=0 and k2=7 ignored), write y ----
    for (int task = tid; task < 14 * NC; task += NTHR) {
        int c = task & (NC - 1);
        int p = task / NC;
        float er[8], ei[8];
        #pragma unroll
        for (int k2 = 0; k2 < 8; k2++) {
            er[k2] = Er[(p * 8 + k2) * NC + c];
            ei[k2] = Ei[(p * 8 + k2) * NC + c];
        }
        float* yout = y + ((b * 196) + p * 14) * 512 + c0 + c;
        #pragma unroll
        for (int q = 0; q < 14; q++) {
            float v = er[0] + ((q & 1) ? -er[7] : er[7]);
            #pragma unroll
            for (int k2 = 1; k2 < 7; k2++) {
                const int m = (k2 * q) % 14;
                v += er[k2] * (2.0f * CC[m]) - ei[k2] * (2.0f * SS[m]);
            }
            yout[q * 512] = v;
        }
    }
}

extern "C" void kernel_launch(void* const* d_in, const int* in_sizes, int n_in,
                              void* d_out, int out_size) {
    const float* x = (const float*)d_in[0];        // [256,196,512] f32
    const float* w = (const float*)d_in[1];        // [14,8,512,2]  f32
    float* y = (float*)d_out;                      // [256,196,512] f32

    const int smem_bytes = (196 * NC + 2 * 14 * 8 * NC) * (int)sizeof(float); // 53760
    cudaFuncSetAttribute(gf_kernel, cudaFuncAttributeMaxDynamicSharedMemorySize,
                         smem_bytes);

    dim3 grid(512 / NC, 256);
    gf_kernel<<<grid, NTHR, smem_bytes>>>(x, w, y);
}

// round 2
// speedup vs baseline: 1.5225x; 1.5225x over previous
#include <cuda_runtime.h>

// GlobalFilter: y = irfft2(rfft2(x, ortho) * W, ortho), spatial 14x14, B=256, C=512.
// Fused single kernel; all 14-point DFTs use even/odd input folding + output
// pairing (k <-> 14-k share cos/sin product groups) to halve FMA count.

#define NC 32          // channels per CTA
#define NTHR 256

__global__ __launch_bounds__(NTHR) void gf_kernel(const float* __restrict__ x,
                                                  const float* __restrict__ w,
                                                  float* __restrict__ y) {
    extern __shared__ float sm[];
    float* xs = sm;                 // [196][NC]
    float* Er = xs + 196 * NC;      // [14][8][NC]
    float* Ei = Er + 14 * 8 * NC;   // [14][8][NC]

    const int b  = blockIdx.y;
    const int c0 = blockIdx.x * NC;
    const int tid = threadIdx.x;

    // cos/sin(2*pi*m/14), m = 0..13
    const float CC[14] = {
         1.0000000000000000f,  0.9009688679024191f,  0.6234898018587336f,
         0.2225209339563144f, -0.2225209339563143f, -0.6234898018587335f,
        -0.9009688679024191f, -1.0000000000000000f, -0.9009688679024191f,
        -0.6234898018587336f, -0.2225209339563146f,  0.2225209339563143f,
         0.6234898018587334f,  0.9009688679024190f
    };
    const float SS[14] = {
         0.0000000000000000f,  0.4338837391175581f,  0.7818314824680298f,
         0.9749279121818236f,  0.9749279121818236f,  0.7818314824680299f,
         0.4338837391175582f,  0.0000000000000000f, -0.4338837391175581f,
        -0.7818314824680297f, -0.9749279121818236f, -0.9749279121818238f,
        -0.7818314824680300f, -0.4338837391175583f
    };

    // ---- Load x tile ----
    {
        const float4* xin = reinterpret_cast<const float4*>(x + (b * 196) * 512 + c0);
        float4* xs4 = reinterpret_cast<float4*>(xs);
        #pragma unroll 2
        for (int i = tid; i < 196 * (NC / 4); i += NTHR) {
            int n  = i >> 3;
            int c4 = i & 7;
            xs4[n * (NC / 4) + c4] = xin[n * 128 + c4];
        }
    }
    __syncthreads();

    // ---- Stage A: rfft along q. tasks = 14*NC = 448 ----
    for (int task = tid; task < 14 * NC; task += NTHR) {
        int c = task & (NC - 1);
        int p = task / NC;
        float xr[14];
        #pragma unroll
        for (int q = 0; q < 14; q++) xr[q] = xs[(p * 14 + q) * NC + c];
        const float x0 = xr[0], x7 = xr[7];
        float xe[7], xo[7];
        #pragma unroll
        for (int j = 1; j <= 6; j++) { xe[j] = xr[j] + xr[14 - j]; xo[j] = xr[j] - xr[14 - j]; }

        // k2 = 0: pure sum (adds only)
        {
            float er = x0 + x7;
            #pragma unroll
            for (int j = 1; j <= 6; j++) er += xe[j];
            Er[(p * 8 + 0) * NC + c] = er;
            Ei[(p * 8 + 0) * NC + c] = 0.0f;
        }
        // k2 = 7: alternating sum (adds only)
        {
            float er = x0 - x7;
            #pragma unroll
            for (int j = 1; j <= 6; j++) er += (j & 1) ? -xe[j] : xe[j];
            Er[(p * 8 + 7) * NC + c] = er;
            Ei[(p * 8 + 7) * NC + c] = 0.0f;
        }
        // k2 = 1..6
        #pragma unroll
        for (int k2 = 1; k2 <= 6; k2++) {
            float er = x0 + ((k2 & 1) ? -x7 : x7);
            float ei = 0.0f;
            #pragma unroll
            for (int j = 1; j <= 6; j++) {
                const int m = (k2 * j) % 14;
                er += xe[j] * CC[m];
                ei -= xo[j] * SS[m];
            }
            Er[(p * 8 + k2) * NC + c] = er;
            Ei[(p * 8 + k2) * NC + c] = ei;
        }
    }
    __syncthreads();

    // ---- Stage B: fft over p, * W/196, ifft over p. One task per thread. ----
    {
        const int task = tid;              // 8*NC == NTHR
        const int c  = task & (NC - 1);
        const int k2 = task / NC;

        // load + input fold over p
        float er0 = Er[(0 * 8 + k2) * NC + c];
        float ei0 = Ei[(0 * 8 + k2) * NC + c];
        float er7 = Er[(7 * 8 + k2) * NC + c];
        float ei7 = Ei[(7 * 8 + k2) * NC + c];
        float ser[7], der[7], sei[7], dei[7];
        #pragma unroll
        for (int j = 1; j <= 6; j++) {
            float ra = Er[(j * 8 + k2) * NC + c];
            float rb = Er[((14 - j) * 8 + k2) * NC + c];
            float ia = Ei[(j * 8 + k2) * NC + c];
            float ib = Ei[((14 - j) * 8 + k2) * NC + c];
            ser[j] = ra + rb; der[j] = ra - rb;
            sei[j] = ia + ib; dei[j] = ia - ib;
        }

        float zr[14], zi[14];
        // k1 = 0 / 7 (adds only)
        {
            float r = er0 + er7, i = ei0 + ei7;
            float r7 = er0 - er7, i7 = ei0 - ei7;
            #pragma unroll
            for (int j = 1; j <= 6; j++) {
                r += ser[j]; i += sei[j];
                r7 += (j & 1) ? -ser[j] : ser[j];
                i7 += (j & 1) ? -sei[j] : sei[j];
            }
            zr[0] = r; zi[0] = i; zr[7] = r7; zi[7] = i7;
        }
        // k1 pairs (k1, 14-k1), k1 = 1..6: share product groups A,B,C,D
        #pragma unroll
        for (int k1 = 1; k1 <= 6; k1++) {
            float A = 0.f, B = 0.f, C = 0.f, D = 0.f;
            #pragma unroll
            for (int j = 1; j <= 6; j++) {
                const int m = (k1 * j) % 14;
                A += ser[j] * CC[m];
                B += dei[j] * SS[m];
                C += sei[j] * CC[m];
                D += der[j] * SS[m];
            }
            const float baseR = er0 + ((k1 & 1) ? -er7 : er7);
            const float baseI = ei0 + ((k1 & 1) ? -ei7 : ei7);
            zr[k1]      = baseR + A + B;
            zr[14 - k1] = baseR + A - B;
            zi[k1]      = baseI + C - D;
            zi[14 - k1] = baseI + C + D;
        }

        // pointwise complex weight (1/196 folded in)
        const float inv196 = 1.0f / 196.0f;
        #pragma unroll
        for (int k1 = 0; k1 < 14; k1++) {
            float2 wv = *reinterpret_cast<const float2*>(
                w + (((k1 * 8 + k2) * 512) + c0 + c) * 2);
            float wr = wv.x * inv196, wi = wv.y * inv196;
            float ar = zr[k1] * wr - zi[k1] * wi;
            float ai = zr[k1] * wi + zi[k1] * wr;
            zr[k1] = ar; zi[k1] = ai;
        }

        // inverse fft over p (e^{+i theta}), folded + output-paired
        float sZr[7], dZr[7], sZi[7], dZi[7];
        #pragma unroll
        for (int j = 1; j <= 6; j++) {
            sZr[j] = zr[j] + zr[14 - j]; dZr[j] = zr[j] - zr[14 - j];
            sZi[j] = zi[j] + zi[14 - j]; dZi[j] = zi[j] - zi[14 - j];
        }
        // p = 0 / 7
        {
            float r = zr[0] + zr[7], i = zi[0] + zi[7];
            float r7 = zr[0] - zr[7], i7 = zi[0] - zi[7];
            #pragma unroll
            for (int j = 1; j <= 6; j++) {
                r += sZr[j]; i += sZi[j];
                r7 += (j & 1) ? -sZr[j] : sZr[j];
                i7 += (j & 1) ? -sZi[j] : sZi[j];
            }
            Er[(0 * 8 + k2) * NC + c] = r;  Ei[(0 * 8 + k2) * NC + c] = i;
            Er[(7 * 8 + k2) * NC + c] = r7; Ei[(7 * 8 + k2) * NC + c] = i7;
        }
        // p pairs (p, 14-p), p = 1..6
        #pragma unroll
        for (int p = 1; p <= 6; p++) {
            float A = 0.f, B = 0.f, C = 0.f, D = 0.f;
            #pragma unroll
            for (int j = 1; j <= 6; j++) {
                const int m = (p * j) % 14;
                A += sZr[j] * CC[m];
                B += dZi[j] * SS[m];
                C += sZi[j] * CC[m];
                D += dZr[j] * SS[m];
            }
            const float baseR = zr[0] + ((p & 1) ? -zr[7] : zr[7]);
            const float baseI = zi[0] + ((p & 1) ? -zi[7] : zi[7]);
            Er[(p * 8 + k2) * NC + c]        = baseR + A - B;
            Er[((14 - p) * 8 + k2) * NC + c] = baseR + A + B;
            Ei[(p * 8 + k2) * NC + c]        = baseI + C + D;
            Ei[((14 - p) * 8 + k2) * NC + c] = baseI + C - D;
        }
    }
    __syncthreads();

    // ---- Stage A': irfft along q, output-paired over q. ----
    for (int task = tid; task < 14 * NC; task += NTHR) {
        int c = task & (NC - 1);
        int p = task / NC;
        float er[8], ei[8];
        #pragma unroll
        for (int k2 = 0; k2 < 8; k2++) {
            er[k2] = Er[(p * 8 + k2) * NC + c];
            ei[k2] = Ei[(p * 8 + k2) * NC + c];
        }
        float* yout = y + ((b * 196) + p * 14) * 512 + c0 + c;

        // q = 0 / 7 (adds only)
        {
            float v0 = er[0] + er[7];
            float v7 = er[0] - er[7];
            #pragma unroll
            for (int k2 = 1; k2 <= 6; k2++) {
                v0 += 2.0f * er[k2];
                v7 += (k2 & 1) ? -2.0f * er[k2] : 2.0f * er[k2];
            }
            yout[0]       = v0;
            yout[7 * 512] = v7;
        }
        // q pairs (q, 14-q), q = 1..6
        #pragma unroll
        for (int q = 1; q <= 6; q++) {
            float A = 0.f, B = 0.f;
            #pragma unroll
            for (int k2 = 1; k2 <= 6; k2++) {
                const int m = (k2 * q) % 14;
                A += er[k2] * (2.0f * CC[m]);
                B += ei[k2] * (2.0f * SS[m]);
            }
            const float base = er[0] + ((q & 1) ? -er[7] : er[7]);
            yout[q * 512]        = base + A - B;
            yout[(14 - q) * 512] = base + A + B;
        }
    }
}

extern "C" void kernel_launch(void* const* d_in, const int* in_sizes, int n_in,
                              void* d_out, int out_size) {
    const float* x = (const float*)d_in[0];        // [256,196,512] f32
    const float* w = (const float*)d_in[1];        // [14,8,512,2]  f32
    float* y = (float*)d_out;                      // [256,196,512] f32

    const int smem_bytes = (196 * NC + 2 * 14 * 8 * NC) * (int)sizeof(float); // 53760
    cudaFuncSetAttribute(gf_kernel, cudaFuncAttributeMaxDynamicSharedMemorySize,
                         smem_bytes);

    dim3 grid(512 / NC, 256);
    gf_kernel<<<grid, NTHR, smem_bytes>>>(x, w, y);
}

// round 4
// speedup vs baseline: 2.0054x; 1.3172x over previous
#include <cuda_runtime.h>

// GlobalFilter: y = irfft2(rfft2(x, ortho) * W, ortho), 14x14 spatial, B=256, C=512.
// R3 (resubmit after infra failure): complex lanes packed into f32x2
// (fma.rn.f32x2 / add/sub/mul.rn.f32x2), xs staging tile removed (stage A reads
// x coalesced from global), smem = interleaved complex E only (28KB).

#define NC 32
#define NTHR 256

typedef unsigned long long u64;

__device__ __forceinline__ u64 pk2(float x, float y) {
    u64 r; asm("mov.b64 %0, {%1, %2};" : "=l"(r) : "f"(x), "f"(y)); return r;
}
__device__ __forceinline__ void upk2(u64 v, float& x, float& y) {
    asm("mov.b64 {%0, %1}, %2;" : "=f"(x), "=f"(y) : "l"(v));
}
__device__ __forceinline__ u64 f2fma(u64 a, u64 b, u64 c) {
    u64 d; asm("fma.rn.f32x2 %0, %1, %2, %3;" : "=l"(d) : "l"(a), "l"(b), "l"(c)); return d;
}
__device__ __forceinline__ u64 f2add(u64 a, u64 b) {
    u64 d; asm("add.rn.f32x2 %0, %1, %2;" : "=l"(d) : "l"(a), "l"(b)); return d;
}
__device__ __forceinline__ u64 f2sub(u64 a, u64 b) {
    u64 d; asm("sub.rn.f32x2 %0, %1, %2;" : "=l"(d) : "l"(a), "l"(b)); return d;
}
__device__ __forceinline__ u64 f2mul(u64 a, u64 b) {
    u64 d; asm("mul.rn.f32x2 %0, %1, %2;" : "=l"(d) : "l"(a), "l"(b)); return d;
}

__global__ __launch_bounds__(NTHR, 4) void gf_kernel(const float* __restrict__ x,
                                                     const float* __restrict__ w,
                                                     float* __restrict__ y) {
    __shared__ u64 E[14 * 8 * NC];   // interleaved complex (re, im), 28672 B

    const int b  = blockIdx.y;
    const int c0 = blockIdx.x * NC;
    const int tid = threadIdx.x;

    // cos/sin(2*pi*m/14), m = 0..13
    const float CC[14] = {
         1.0000000000000000f,  0.9009688679024191f,  0.6234898018587336f,
         0.2225209339563144f, -0.2225209339563143f, -0.6234898018587335f,
        -0.9009688679024191f, -1.0000000000000000f, -0.9009688679024191f,
        -0.6234898018587336f, -0.2225209339563146f,  0.2225209339563143f,
         0.6234898018587334f,  0.9009688679024190f
    };
    const float SS[14] = {
         0.0000000000000000f,  0.4338837391175581f,  0.7818314824680298f,
         0.9749279121818236f,  0.9749279121818236f,  0.7818314824680299f,
         0.4338837391175582f,  0.0000000000000000f, -0.4338837391175581f,
        -0.7818314824680297f, -0.9749279121818236f, -0.9749279121818238f,
        -0.7818314824680300f, -0.4338837391175583f
    };

    // ---- Stage A: rfft along q, direct from global. tasks = 14*NC = 448 ----
    for (int task = tid; task < 14 * NC; task += NTHR) {
        const int c = task & (NC - 1);
        const int p = task >> 5;
        const float* xp = x + ((b * 196) + p * 14) * 512 + c0 + c;

        const float x0 = xp[0];
        const float x7 = xp[7 * 512];
        float xe[7], xo[7];
        u64 v[7];
        #pragma unroll
        for (int j = 1; j <= 6; j++) {
            float aa = xp[j * 512], bb = xp[(14 - j) * 512];
            xe[j] = aa + bb; xo[j] = aa - bb;
            v[j] = pk2(xe[j], xo[j]);
        }
        const float bs = x0 + x7, bd = x0 - x7;
        // k2 = 0 / 7 (adds only, imag = 0)
        {
            float e0 = bs, e7 = bd;
            #pragma unroll
            for (int j = 1; j <= 6; j++) {
                e0 += xe[j];
                e7 += (j & 1) ? -xe[j] : xe[j];
            }
            E[(p * 8 + 0) * NC + c] = pk2(e0, 0.0f);
            E[(p * 8 + 7) * NC + c] = pk2(e7, 0.0f);
        }
        // k2 = 1..6: acc lanes = (er, ei), twiddle pair (CC, -SS)
        #pragma unroll
        for (int k2 = 1; k2 <= 6; k2++) {
            u64 acc = pk2((k2 & 1) ? bd : bs, 0.0f);
            #pragma unroll
            for (int j = 1; j <= 6; j++) {
                const int m = (k2 * j) % 14;
                acc = f2fma(v[j], pk2(CC[m], -SS[m]), acc);
            }
            E[(p * 8 + k2) * NC + c] = acc;
        }
    }
    __syncthreads();

    // ---- Stage B: fft over p, * W/196, ifft over p. One task per thread. ----
    {
        const int c  = tid & (NC - 1);
        const int k2 = tid >> 5;
        u64* col = E + k2 * NC + c;          // element (p) at col[p * 8*NC]
        const int PS = 8 * NC;               // 256

        const u64 e0 = col[0];
        const u64 e7 = col[7 * PS];
        u64 s[7], d[7];
        #pragma unroll
        for (int j = 1; j <= 6; j++) {
            u64 a = col[j * PS], bb = col[(14 - j) * PS];
            s[j] = f2add(a, bb);             // (ser, sei)
            d[j] = f2sub(a, bb);             // (der, dei)
        }

        u64 z[14];
        const u64 bp = f2add(e0, e7);        // (baseR, baseI) for even k1
        const u64 bm = f2sub(e0, e7);        // for odd k1
        // k1 = 0 / 7 (packed adds)
        {
            u64 z0 = bp, z7 = bm;
            #pragma unroll
            for (int j = 1; j <= 6; j++) {
                z0 = f2add(z0, s[j]);
                z7 = (j & 1) ? f2sub(z7, s[j]) : f2add(z7, s[j]);
            }
            z[0] = z0; z[7] = z7;
        }
        // k1 pairs 1..6: AC lanes=(A,C) from s*CC; DB lanes=(D,B) from d*SS
        #pragma unroll
        for (int k1 = 1; k1 <= 6; k1++) {
            u64 AC = f2mul(s[1], pk2(CC[k1 % 14], CC[k1 % 14]));
            u64 DB = f2mul(d[1], pk2(SS[k1 % 14], SS[k1 % 14]));
            #pragma unroll
            for (int j = 2; j <= 6; j++) {
                const int m = (k1 * j) % 14;
                AC = f2fma(s[j], pk2(CC[m], CC[m]), AC);
                DB = f2fma(d[j], pk2(SS[m], SS[m]), DB);
            }
            float A, C, D, Bv, bR, bI;
            upk2(AC, A, C); upk2(DB, D, Bv);
            upk2((k1 & 1) ? bm : bp, bR, bI);
            z[k1]      = pk2(bR + A + Bv, bI + C - D);
            z[14 - k1] = pk2(bR + A - Bv, bI + C + D);
        }

        // pointwise complex weight (1/196 folded in)
        const float inv196 = 1.0f / 196.0f;
        const float2* wp = reinterpret_cast<const float2*>(w) + k2 * 512 + c0 + c;
        #pragma unroll
        for (int k1 = 0; k1 < 14; k1++) {
            float2 wv = wp[k1 * 8 * 512];
            float zr, zi; upk2(z[k1], zr, zi);
            const float wr = wv.x * inv196, wi = wv.y * inv196;
            z[k1] = pk2(zr * wr - zi * wi, zr * wi + zi * wr);
        }

        // inverse fft over p (e^{+i theta})
        const u64 zp = f2add(z[0], z[7]);
        const u64 zm = f2sub(z[0], z[7]);
        u64 s2[7], d2[7];
        #pragma unroll
        for (int j = 1; j <= 6; j++) {
            s2[j] = f2add(z[j], z[14 - j]);  // (sZr, sZi)
            d2[j] = f2sub(z[j], z[14 - j]);  // (dZr, dZi)
        }
        // p = 0 / 7
        {
            u64 o0 = zp, o7 = zm;
            #pragma unroll
            for (int j = 1; j <= 6; j++) {
                o0 = f2add(o0, s2[j]);
                o7 = (j & 1) ? f2sub(o7, s2[j]) : f2add(o7, s2[j]);
            }
            col[0]      = o0;
            col[7 * PS] = o7;
        }
        // p pairs 1..6: AC2 lanes=(A,C); DB2 lanes=(D,B)
        #pragma unroll
        for (int p = 1; p <= 6; p++) {
            u64 AC = f2mul(s2[1], pk2(CC[p % 14], CC[p % 14]));
            u64 DB = f2mul(d2[1], pk2(SS[p % 14], SS[p % 14]));
            #pragma unroll
            for (int j = 2; j <= 6; j++) {
                const int m = (p * j) % 14;
                AC = f2fma(s2[j], pk2(CC[m], CC[m]), AC);
                DB = f2fma(d2[j], pk2(SS[m], SS[m]), DB);
            }
            float A, C, D, Bv, bR, bI;
            upk2(AC, A, C); upk2(DB, D, Bv);
            upk2((p & 1) ? zm : zp, bR, bI);
            col[p * PS]        = pk2(bR + A - Bv, bI + C + D);
            col[(14 - p) * PS] = pk2(bR + A + Bv, bI + C - D);
        }
    }
    __syncthreads();

    // ---- Stage A': irfft along q, write y. tasks = 14*NC = 448 ----
    for (int task = tid; task < 14 * NC; task += NTHR) {
        const int c = task & (NC - 1);
        const int p = task >> 5;
        const u64* row = E + (p * 8) * NC + c;

        float er[8], ei[8];
        u64 e[8];
        #pragma unroll
        for (int k2 = 0; k2 < 8; k2++) {
            e[k2] = row[k2 * NC];
            upk2(e[k2], er[k2], ei[k2]);
        }
        float* yout = y + ((b * 196) + p * 14) * 512 + c0 + c;

        // q = 0 / 7 (adds only)
        {
            float v0 = er[0] + er[7];
            float v7 = er[0] - er[7];
            #pragma unroll
            for (int k2 = 1; k2 <= 6; k2++) {
                v0 += 2.0f * er[k2];
                v7 += (k2 & 1) ? -2.0f * er[k2] : 2.0f * er[k2];
            }
            yout[0]       = v0;
            yout[7 * 512] = v7;
        }
        // q pairs 1..6: AB lanes = (A, B) from e * (2CC, 2SS)
        #pragma unroll
        for (int q = 1; q <= 6; q++) {
            u64 AB = f2mul(e[1], pk2(2.0f * CC[q % 14], 2.0f * SS[q % 14]));
            #pragma unroll
            for (int k2 = 2; k2 <= 6; k2++) {
                const int m = (k2 * q) % 14;
                AB = f2fma(e[k2], pk2(2.0f * CC[m], 2.0f * SS[m]), AB);
            }
            float A, Bv; upk2(AB, A, Bv);
            const float base = er[0] + ((q & 1) ? -er[7] : er[7]);
            yout[q * 512]        = base + A - Bv;
            yout[(14 - q) * 512] = base + A + Bv;
        }
    }
}

extern "C" void kernel_launch(void* const* d_in, const int* in_sizes, int n_in,
                              void* d_out, int out_size) {
    const float* x = (const float*)d_in[0];        // [256,196,512] f32
    const float* w = (const float*)d_in[1];        // [14,8,512,2]  f32
    float* y = (float*)d_out;                      // [256,196,512] f32

    dim3 grid(512 / NC, 256);
    gf_kernel<<<grid, NTHR>>>(x, w, y);
}

// round 5
// speedup vs baseline: 2.1646x; 1.0794x over previous
#include <cuda_runtime.h>

// GlobalFilter: y = irfft2(rfft2(x, ortho) * W, ortho), 14x14 spatial, B=256, C=512.
// R5: latency hiding — stages A/A' restructured as two explicit task slots with
//     all loads issued up front (28 LDG / 16 LDS in flight), stage-B weight
//     loads fused into the k1-pair loop (L2 latency hidden under FFT math).

#define NC 32
#define NTHR 256

typedef unsigned long long u64;

__device__ __forceinline__ u64 pk2(float x, float y) {
    u64 r; asm("mov.b64 %0, {%1, %2};" : "=l"(r) : "f"(x), "f"(y)); return r;
}
__device__ __forceinline__ void upk2(u64 v, float& x, float& y) {
    asm("mov.b64 {%0, %1}, %2;" : "=f"(x), "=f"(y) : "l"(v));
}
__device__ __forceinline__ u64 f2fma(u64 a, u64 b, u64 c) {
    u64 d; asm("fma.rn.f32x2 %0, %1, %2, %3;" : "=l"(d) : "l"(a), "l"(b), "l"(c)); return d;
}
__device__ __forceinline__ u64 f2add(u64 a, u64 b) {
    u64 d; asm("add.rn.f32x2 %0, %1, %2;" : "=l"(d) : "l"(a), "l"(b)); return d;
}
__device__ __forceinline__ u64 f2sub(u64 a, u64 b) {
    u64 d; asm("sub.rn.f32x2 %0, %1, %2;" : "=l"(d) : "l"(a), "l"(b)); return d;
}
__device__ __forceinline__ u64 f2mul(u64 a, u64 b) {
    u64 d; asm("mul.rn.f32x2 %0, %1, %2;" : "=l"(d) : "l"(a), "l"(b)); return d;
}

__global__ __launch_bounds__(NTHR, 4) void gf_kernel(const float* __restrict__ x,
                                                     const float* __restrict__ w,
                                                     float* __restrict__ y) {
    __shared__ u64 E[14 * 8 * NC];   // interleaved complex (re, im), 28672 B

    const int b  = blockIdx.y;
    const int c0 = blockIdx.x * NC;
    const int tid = threadIdx.x;

    const float CC[14] = {
         1.0000000000000000f,  0.9009688679024191f,  0.6234898018587336f,
         0.2225209339563144f, -0.2225209339563143f, -0.6234898018587335f,
        -0.9009688679024191f, -1.0000000000000000f, -0.9009688679024191f,
        -0.6234898018587336f, -0.2225209339563146f,  0.2225209339563143f,
         0.6234898018587334f,  0.9009688679024190f
    };
    const float SS[14] = {
         0.0000000000000000f,  0.4338837391175581f,  0.7818314824680298f,
         0.9749279121818236f,  0.9749279121818236f,  0.7818314824680299f,
         0.4338837391175582f,  0.0000000000000000f, -0.4338837391175581f,
        -0.7818314824680297f, -0.9749279121818236f, -0.9749279121818238f,
        -0.7818314824680300f, -0.4338837391175583f
    };

    const int c  = tid & (NC - 1);
    const int p0 = tid >> 5;                 // 0..7
    const bool two = (tid < 192);            // second task has p1 = p0 + 8 (8..13)

    // ---- Stage A: rfft along q. Two task slots, all LDGs issued up front. ----
    {
        const float* xp0 = x + ((b * 196) + p0 * 14) * 512 + c0 + c;
        const float* xp1 = xp0 + 8 * 14 * 512;   // p1 = p0 + 8

        float r0[14], r1[14];
        #pragma unroll
        for (int q = 0; q < 14; q++) r0[q] = xp0[q * 512];
        if (two) {
            #pragma unroll
            for (int q = 0; q < 14; q++) r1[q] = xp1[q * 512];
        }

        // task 0
        {
            const float x0 = r0[0], x7 = r0[7];
            float xe[7];
            u64 v[7];
            #pragma unroll
            for (int j = 1; j <= 6; j++) {
                float aa = r0[j], bb = r0[14 - j];
                xe[j] = aa + bb;
                v[j] = pk2(aa + bb, aa - bb);
            }
            const float bs = x0 + x7, bd = x0 - x7;
            float e0 = bs, e7 = bd;
            #pragma unroll
            for (int j = 1; j <= 6; j++) {
                e0 += xe[j];
                e7 += (j & 1) ? -xe[j] : xe[j];
            }
            E[(p0 * 8 + 0) * NC + c] = pk2(e0, 0.0f);
            E[(p0 * 8 + 7) * NC + c] = pk2(e7, 0.0f);
            #pragma unroll
            for (int k2 = 1; k2 <= 6; k2++) {
                u64 acc = pk2((k2 & 1) ? bd : bs, 0.0f);
                #pragma unroll
                for (int j = 1; j <= 6; j++) {
                    const int m = (k2 * j) % 14;
                    acc = f2fma(v[j], pk2(CC[m], -SS[m]), acc);
                }
                E[(p0 * 8 + k2) * NC + c] = acc;
            }
        }
        // task 1 (predicated)
        if (two) {
            const int p1 = p0 + 8;
            const float x0 = r1[0], x7 = r1[7];
            float xe[7];
            u64 v[7];
            #pragma unroll
            for (int j = 1; j <= 6; j++) {
                float aa = r1[j], bb = r1[14 - j];
                xe[j] = aa + bb;
                v[j] = pk2(aa + bb, aa - bb);
            }
            const float bs = x0 + x7, bd = x0 - x7;
            float e0 = bs, e7 = bd;
            #pragma unroll
            for (int j = 1; j <= 6; j++) {
                e0 += xe[j];
                e7 += (j & 1) ? -xe[j] : xe[j];
            }
            E[(p1 * 8 + 0) * NC + c] = pk2(e0, 0.0f);
            E[(p1 * 8 + 7) * NC + c] = pk2(e7, 0.0f);
            #pragma unroll
            for (int k2 = 1; k2 <= 6; k2++) {
                u64 acc = pk2((k2 & 1) ? bd : bs, 0.0f);
                #pragma unroll
                for (int j = 1; j <= 6; j++) {
                    const int m = (k2 * j) % 14;
                    acc = f2fma(v[j], pk2(CC[m], -SS[m]), acc);
                }
                E[(p1 * 8 + k2) * NC + c] = acc;
            }
        }
    }
    __syncthreads();

    // ---- Stage B: fft over p, * W/196 (fused into pair loop), ifft over p. ----
    {
        const int k2 = tid >> 5;
        u64* col = E + k2 * NC + c;          // element (p) at col[p * 8*NC]
        const int PS = 8 * NC;               // 256

        const u64 e0 = col[0];
        const u64 e7 = col[7 * PS];
        u64 s[7], d[7];
        #pragma unroll
        for (int j = 1; j <= 6; j++) {
            u64 a = col[j * PS], bb = col[(14 - j) * PS];
            s[j] = f2add(a, bb);             // (ser, sei)
            d[j] = f2sub(a, bb);             // (der, dei)
        }

        const float inv196 = 1.0f / 196.0f;
        const float2* wp = reinterpret_cast<const float2*>(w) + k2 * 512 + c0 + c;

        u64 z[14];                           // weighted spectrum
        const u64 bp = f2add(e0, e7);
        const u64 bm = f2sub(e0, e7);
        // k1 = 0 / 7 (packed adds), weight immediately
        {
            const float2 wv0 = wp[0];
            const float2 wv7 = wp[7 * 8 * 512];
            u64 z0 = bp, z7 = bm;
            #pragma unroll
            for (int j = 1; j <= 6; j++) {
                z0 = f2add(z0, s[j]);
                z7 = (j & 1) ? f2sub(z7, s[j]) : f2add(z7, s[j]);
            }
            float zr, zi;
            upk2(z0, zr, zi);
            { const float wr = wv0.x * inv196, wi = wv0.y * inv196;
              z[0] = pk2(zr * wr - zi * wi, zr * wi + zi * wr); }
            upk2(z7, zr, zi);
            { const float wr = wv7.x * inv196, wi = wv7.y * inv196;
              z[7] = pk2(zr * wr - zi * wi, zr * wi + zi * wr); }
        }
        // k1 pairs 1..6: w loads issued first (L2 latency hides under FMAs)
        #pragma unroll
        for (int k1 = 1; k1 <= 6; k1++) {
            const float2 wvA = wp[k1 * 8 * 512];
            const float2 wvB = wp[(14 - k1) * 8 * 512];
            u64 AC = f2mul(s[1], pk2(CC[k1 % 14], CC[k1 % 14]));
            u64 DB = f2mul(d[1], pk2(SS[k1 % 14], SS[k1 % 14]));
            #pragma unroll
            for (int j = 2; j <= 6; j++) {
                const int m = (k1 * j) % 14;
                AC = f2fma(s[j], pk2(CC[m], CC[m]), AC);
                DB = f2fma(d[j], pk2(SS[m], SS[m]), DB);
            }
            float A, C, D, Bv, bR, bI;
            upk2(AC, A, C); upk2(DB, D, Bv);
            upk2((k1 & 1) ? bm : bp, bR, bI);
            const float zra = bR + A + Bv, zia = bI + C - D;     // k1
            const float zrb = bR + A - Bv, zib = bI + C + D;     // 14-k1
            { const float wr = wvA.x * inv196, wi = wvA.y * inv196;
              z[k1] = pk2(zra * wr - zia * wi, zra * wi + zia * wr); }
            { const float wr = wvB.x * inv196, wi = wvB.y * inv196;
              z[14 - k1] = pk2(zrb * wr - zib * wi, zrb * wi + zib * wr); }
        }

        // inverse fft over p (e^{+i theta})
        const u64 zp = f2add(z[0], z[7]);
        const u64 zm = f2sub(z[0], z[7]);
        u64 s2[7], d2[7];
        #pragma unroll
        for (int j = 1; j <= 6; j++) {
            s2[j] = f2add(z[j], z[14 - j]);
            d2[j] = f2sub(z[j], z[14 - j]);
        }
        {
            u64 o0 = zp, o7 = zm;
            #pragma unroll
            for (int j = 1; j <= 6; j++) {
                o0 = f2add(o0, s2[j]);
                o7 = (j & 1) ? f2sub(o7, s2[j]) : f2add(o7, s2[j]);
            }
            col[0]      = o0;
            col[7 * PS] = o7;
        }
        #pragma unroll
        for (int p = 1; p <= 6; p++) {
            u64 AC = f2mul(s2[1], pk2(CC[p % 14], CC[p % 14]));
            u64 DB = f2mul(d2[1], pk2(SS[p % 14], SS[p % 14]));
            #pragma unroll
            for (int j = 2; j <= 6; j++) {
                const int m = (p * j) % 14;
                AC = f2fma(s2[j], pk2(CC[m], CC[m]), AC);
                DB = f2fma(d2[j], pk2(SS[m], SS[m]), DB);
            }
            float A, C, D, Bv, bR, bI;
            upk2(AC, A, C); upk2(DB, D, Bv);
            upk2((p & 1) ? zm : zp, bR, bI);
            col[p * PS]        = pk2(bR + A - Bv, bI + C + D);
            col[(14 - p) * PS] = pk2(bR + A + Bv, bI + C - D);
        }
    }
    __syncthreads();

    // ---- Stage A': irfft along q, two task slots, all LDS issued up front. ----
    {
        const u64* row0 = E + (p0 * 8) * NC + c;
        const u64* row1 = row0 + 8 * 8 * NC;         // p1 = p0 + 8
        u64 ea[8], eb[8];
        #pragma unroll
        for (int k2 = 0; k2 < 8; k2++) ea[k2] = row0[k2 * NC];
        if (two) {
            #pragma unroll
            for (int k2 = 0; k2 < 8; k2++) eb[k2] = row1[k2 * NC];
        }

        float* yout0 = y + ((b * 196) + p0 * 14) * 512 + c0 + c;

        // task 0
        {
            float er[8], ei[8];
            #pragma unroll
            for (int k2 = 0; k2 < 8; k2++) upk2(ea[k2], er[k2], ei[k2]);
            float v0 = er[0] + er[7];
            float v7 = er[0] - er[7];
            #pragma unroll
            for (int k2 = 1; k2 <= 6; k2++) {
                v0 += 2.0f * er[k2];
                v7 += (k2 & 1) ? -2.0f * er[k2] : 2.0f * er[k2];
            }
            yout0[0]       = v0;
            yout0[7 * 512] = v7;
            #pragma unroll
            for (int q = 1; q <= 6; q++) {
                u64 AB = f2mul(ea[1], pk2(2.0f * CC[q % 14], 2.0f * SS[q % 14]));
                #pragma unroll
                for (int k2 = 2; k2 <= 6; k2++) {
                    const int m = (k2 * q) % 14;
                    AB = f2fma(ea[k2], pk2(2.0f * CC[m], 2.0f * SS[m]), AB);
                }
                float A, Bv; upk2(AB, A, Bv);
                const float base = er[0] + ((q & 1) ? -er[7] : er[7]);
                yout0[q * 512]        = base + A - Bv;
                yout0[(14 - q) * 512] = base + A + Bv;
            }
        }
        // task 1 (predicated)
        if (two) {
            float* yout1 = yout0 + 8 * 14 * 512;
            float er[8], ei[8];
            #pragma unroll
            for (int k2 = 0; k2 < 8; k2++) upk2(eb[k2], er[k2], ei[k2]);
            float v0 = er[0] + er[7];
            float v7 = er[0] - er[7];
            #pragma unroll
            for (int k2 = 1; k2 <= 6; k2++) {
                v0 += 2.0f * er[k2];
                v7 += (k2 & 1) ? -2.0f * er[k2] : 2.0f * er[k2];
            }
            yout1[0]       = v0;
            yout1[7 * 512] = v7;
            #pragma unroll
            for (int q = 1; q <= 6; q++) {
                u64 AB = f2mul(eb[1], pk2(2.0f * CC[q % 14], 2.0f * SS[q % 14]));
                #pragma unroll
                for (int k2 = 2; k2 <= 6; k2++) {
                    const int m = (k2 * q) % 14;
                    AB = f2fma(eb[k2], pk2(2.0f * CC[m], 2.0f * SS[m]), AB);
                }
                float A, Bv; upk2(AB, A, Bv);
                const float base = er[0] + ((q & 1) ? -er[7] : er[7]);
                yout1[q * 512]        = base + A - Bv;
                yout1[(14 - q) * 512] = base + A + Bv;
            }
        }
    }
}

extern "C" void kernel_launch(void* const* d_in, const int* in_sizes, int n_in,
                              void* d_out, int out_size) {
    const float* x = (const float*)d_in[0];        // [256,196,512] f32
    const float* w = (const float*)d_in[1];        // [14,8,512,2]  f32
    float* y = (float*)d_out;                      // [256,196,512] f32

    dim3 grid(512 / NC, 256);
    gf_kernel<<<grid, NTHR>>>(x, w, y);
}